// round 14
// baseline (speedup 1.0000x reference)
#include <cuda_runtime.h>

// ----------------------------------------------------------------------------
// NeighborAttention (63 GFLOP -> 3.9 GFLOP), 5 launches:
//   1) Q   = hV @ WQ^T
//   2) Qt  = (1/sqrt(32)) * Q_h @ WK_h
//   3) attn: persistent, pipelined; broadcast smem reads replaced by shuffles
//   4) vout = ctx_h @ WV_h^T
//   5) out  = vout @ WO^T
// ----------------------------------------------------------------------------

#define MAXN 30720
#define HDIM 128
#define KNB 32

__device__ float g_Q[MAXN * 128];
__device__ float g_Qt[MAXN * 512];
__device__ float g_ctx[MAXN * 512];
__device__ float g_vout[MAXN * 128];

// ----------------------------------------------------------------------------
// Tiled SGEMM, 8x8 / 8x4 register microtiles (R10-proven).
// ----------------------------------------------------------------------------
template <int BM, int BN, int BK, int TM, int TN, bool TRANSB>
__global__ void __launch_bounds__((BM / TM) * (BN / TN)) sgemm_kernel(
    const float* __restrict__ A, const float* __restrict__ B, float* __restrict__ C,
    int M, int Nc, int K, int lda, int ldb, int ldc,
    long long aB, long long bB, long long cB, float alpha)
{
    constexpr int NT = (BM / TM) * (BN / TN);
    __shared__ float As[BK][BM + 4];
    __shared__ float Bs[BK][BN + 4];

    const long long bz = blockIdx.z;
    A += bz * aB; B += bz * bB; C += bz * cB;

    const int m0 = blockIdx.y * BM;
    const int n0 = blockIdx.x * BN;
    const int t  = threadIdx.x;
    const int tm = t / (BN / TN);
    const int tn = t % (BN / TN);

    float acc[TM][TN] = {};

    for (int k0 = 0; k0 < K; k0 += BK) {
        constexpr int A4 = (BM * BK) / (4 * NT);
        #pragma unroll
        for (int i = 0; i < A4; i++) {
            int idx4 = t + NT * i;
            int r  = idx4 / (BK / 4);
            int kc = (idx4 % (BK / 4)) * 4;
            float4 v = make_float4(0.f, 0.f, 0.f, 0.f);
            int gr = m0 + r;
            if (gr < M) v = *(const float4*)&A[(long long)gr * lda + k0 + kc];
            As[kc + 0][r] = v.x;
            As[kc + 1][r] = v.y;
            As[kc + 2][r] = v.z;
            As[kc + 3][r] = v.w;
        }
        if (!TRANSB) {
            constexpr int B4 = (BK * BN) / (4 * NT);
            #pragma unroll
            for (int i = 0; i < B4; i++) {
                int idx4 = t + NT * i;
                int kr = idx4 / (BN / 4);
                int nc = (idx4 % (BN / 4)) * 4;
                float4 v = make_float4(0.f, 0.f, 0.f, 0.f);
                if (n0 + nc < Nc) v = *(const float4*)&B[(long long)(k0 + kr) * ldb + n0 + nc];
                *(float4*)&Bs[kr][nc] = v;
            }
        } else {
            constexpr int B4 = (BN * BK) / (4 * NT);
            #pragma unroll
            for (int i = 0; i < B4; i++) {
                int idx4 = t + NT * i;
                int n  = idx4 / (BK / 4);
                int kc = (idx4 % (BK / 4)) * 4;
                float4 v = make_float4(0.f, 0.f, 0.f, 0.f);
                if (n0 + n < Nc) v = *(const float4*)&B[(long long)(n0 + n) * ldb + k0 + kc];
                Bs[kc + 0][n] = v.x;
                Bs[kc + 1][n] = v.y;
                Bs[kc + 2][n] = v.z;
                Bs[kc + 3][n] = v.w;
            }
        }
        __syncthreads();

        #pragma unroll
        for (int kk = 0; kk < BK; kk++) {
            float a[TM], b[TN];
            #pragma unroll
            for (int h = 0; h < TM / 4; h++) {
                float4 v = *(const float4*)&As[kk][tm * 4 + h * (BM / 2)];
                a[h * 4 + 0] = v.x; a[h * 4 + 1] = v.y;
                a[h * 4 + 2] = v.z; a[h * 4 + 3] = v.w;
            }
            #pragma unroll
            for (int h = 0; h < TN / 4; h++) {
                float4 v = *(const float4*)&Bs[kk][tn * 4 + h * (BN / 2)];
                b[h * 4 + 0] = v.x; b[h * 4 + 1] = v.y;
                b[h * 4 + 2] = v.z; b[h * 4 + 3] = v.w;
            }
            #pragma unroll
            for (int i = 0; i < TM; i++)
                #pragma unroll
                for (int j = 0; j < TN; j++)
                    acc[i][j] += a[i] * b[j];
        }
        __syncthreads();
    }

    #pragma unroll
    for (int i = 0; i < TM; i++) {
        int r = m0 + tm * 4 + (i / 4) * (BM / 2) + (i % 4);
        if (r >= M) continue;
        #pragma unroll
        for (int jh = 0; jh < TN / 4; jh++) {
            int c = n0 + tn * 4 + jh * (BN / 2);
            if (c < Nc) {
                float4 v = make_float4(acc[i][jh * 4 + 0] * alpha, acc[i][jh * 4 + 1] * alpha,
                                       acc[i][jh * 4 + 2] * alpha, acc[i][jh * 4 + 3] * alpha);
                *(float4*)&C[(long long)r * ldc + c] = v;
            }
        }
    }
}

// ----------------------------------------------------------------------------
// Persistent fused neighbor attention. Broadcast smem reads (Qt in logits,
// Asm in ctx) replaced by striped register preloads + __shfl_sync, cutting
// L1 wavefront traffic (the measured 89.5%-utilized resource). E staging
// stores are mask-predicated (warp-uniform). Logits/softmax math reads stale
// smem for masked rows; their weights are exactly zero, so results are exact.
// ----------------------------------------------------------------------------
__global__ void __launch_bounds__(128, 6) attn_kernel(
    const float* __restrict__ hE, const int* __restrict__ mask,
    const float* __restrict__ Qt, float* __restrict__ ctx, int N)
{
    __shared__ float Es[32 * 132];
    __shared__ float Qts[4 * 132];
    __shared__ float Lp[512];
    __shared__ float Asm[128];
    __shared__ int   msk[3][32];

    const int t  = threadIdx.x;
    const int G  = gridDim.x;
    const int n0 = blockIdx.x;
    if (n0 >= N) return;

    if (t < 32) {
        msk[0][t] = mask[(long long)n0 * KNB + t];
        long long n1 = n0 + (long long)G;
        msk[1][t] = (n1 < N) ? mask[n1 * KNB + t] : 0;
    }
    __syncthreads();

    float4 ereg[8];
    float4 qreg;

    // --- prologue: load + commit node n0 (masked rows never loaded/stored) ---
    {
        const float* e = hE + (long long)n0 * (KNB * HDIM);
        #pragma unroll
        for (int ii = 0; ii < 8; ii++) {
            int idx4 = t + 128 * ii;
            int k = idx4 >> 5;                       // warp-uniform
            if (msk[0][k]) {
                ereg[ii] = *(const float4*)&e[idx4 << 2];
                int a4 = idx4 & 31;
                *(float4*)&Es[k * 132 + (a4 << 2)] = ereg[ii];
            }
        }
        qreg = *(const float4*)&Qt[(long long)n0 * 512 + t * 4];
        int h = t >> 5, a4 = t & 31;
        *(float4*)&Qts[h * 132 + (a4 << 2)] = qreg;
    }
    __syncthreads();

    for (int i = 0; ; i++) {
        const long long n  = n0 + (long long)i * G;
        const long long nn = n + G;
        const bool has_next = (nn < N);
        int mreg = 0;

        // --- phase A: prefetch node nn into registers (masked rows skipped) ---
        if (has_next) {
            const int s1 = (i + 1) % 3;
            const float* e = hE + nn * (KNB * HDIM);
            #pragma unroll
            for (int ii = 0; ii < 8; ii++) {
                int idx4 = t + 128 * ii;
                int k = idx4 >> 5;                   // warp-uniform
                if (msk[s1][k]) ereg[ii] = *(const float4*)&e[idx4 << 2];
            }
            qreg = *(const float4*)&Qt[nn * 512 + t * 4];
            if (t < 32) {
                long long n2 = n + 2LL * G;
                mreg = (n2 < N) ? mask[n2 * KNB + t] : 0;
            }
        }

        // --- phase B: compute node n from smem ---
        const int* mc = msk[i % 3];

        {   // logits: warp = a-chunk ac, lane = k.
            // Qt values come from striped per-lane registers via shuffle.
            const int ac = t >> 5;
            const int k  = t & 31;
            float qtl[4];
            #pragma unroll
            for (int h = 0; h < 4; h++)
                qtl[h] = Qts[h * 132 + (ac << 5) + k];   // striped, 1 wf each
            const float* ep = &Es[k * 132 + (ac << 5)];
            float p0 = 0.f, p1 = 0.f, p2 = 0.f, p3 = 0.f;
            #pragma unroll
            for (int s = 0; s < 8; s++) {
                float4 e4 = *(const float4*)&ep[s << 2];
                #pragma unroll
                for (int j = 0; j < 4; j++) {
                    float ej = (j == 0) ? e4.x : (j == 1) ? e4.y : (j == 2) ? e4.z : e4.w;
                    p0 += __shfl_sync(0xffffffffu, qtl[0], 4 * s + j) * ej;
                    p1 += __shfl_sync(0xffffffffu, qtl[1], 4 * s + j) * ej;
                    p2 += __shfl_sync(0xffffffffu, qtl[2], 4 * s + j) * ej;
                    p3 += __shfl_sync(0xffffffffu, qtl[3], 4 * s + j) * ej;
                }
            }
            Lp[(ac << 7) + 0 * 32 + k] = p0;
            Lp[(ac << 7) + 1 * 32 + k] = p1;
            Lp[(ac << 7) + 2 * 32 + k] = p2;
            Lp[(ac << 7) + 3 * 32 + k] = p3;
        }
        __syncthreads();

        {   // masked softmax: warp = head, lane = k
            const int h = t >> 5, k = t & 31;
            float x = Lp[0 * 128 + h * 32 + k] + Lp[1 * 128 + h * 32 + k]
                    + Lp[2 * 128 + h * 32 + k] + Lp[3 * 128 + h * 32 + k];
            bool mv  = (mc[k] != 0);
            float xm = mv ? x : -3.402823466e+38f;
            float mx = xm;
            #pragma unroll
            for (int o = 16; o > 0; o >>= 1) mx = fmaxf(mx, __shfl_xor_sync(0xffffffffu, mx, o));
            float p = mv ? __expf(xm - mx) : 0.f;
            float sm = p;
            #pragma unroll
            for (int o = 16; o > 0; o >>= 1) sm += __shfl_xor_sync(0xffffffffu, sm, o);
            float inv = (sm > 0.f) ? (1.f / sm) : 0.f;
            Asm[h * 32 + k] = p * inv;
        }
        __syncthreads();

        {   // ctx: thread t owns column a = t; weights via striped regs + shuffle
            const int l = t & 31;
            float aw0 = Asm[0 * 32 + l];    // striped, 1 wf each
            float aw1 = Asm[1 * 32 + l];
            float aw2 = Asm[2 * 32 + l];
            float aw3 = Asm[3 * 32 + l];
            float c0 = 0.f, c1 = 0.f, c2 = 0.f, c3 = 0.f;
            #pragma unroll
            for (int k = 0; k < 32; k++) {
                float ev = Es[k * 132 + t];
                c0 += __shfl_sync(0xffffffffu, aw0, k) * ev;
                c1 += __shfl_sync(0xffffffffu, aw1, k) * ev;
                c2 += __shfl_sync(0xffffffffu, aw2, k) * ev;
                c3 += __shfl_sync(0xffffffffu, aw3, k) * ev;
            }
            float* cp = ctx + n * 512 + t;
            cp[0]   = c0;
            cp[128] = c1;
            cp[256] = c2;
            cp[384] = c3;
        }

        if (!has_next) break;

        // --- phase C: commit prefetched tile (masked rows not stored) ---
        __syncthreads();
        {
            const int s1 = (i + 1) % 3;
            #pragma unroll
            for (int ii = 0; ii < 8; ii++) {
                int idx4 = t + 128 * ii;
                int k = idx4 >> 5;                   // warp-uniform
                if (msk[s1][k]) {
                    int a4 = idx4 & 31;
                    *(float4*)&Es[k * 132 + (a4 << 2)] = ereg[ii];
                }
            }
            int h = t >> 5, a4 = t & 31;
            *(float4*)&Qts[h * 132 + (a4 << 2)] = qreg;
        }
        if (t < 32) msk[(i + 2) % 3][t] = mreg;
        __syncthreads();
    }
}

// ----------------------------------------------------------------------------
extern "C" void kernel_launch(void* const* d_in, const int* in_sizes, int n_in,
                              void* d_out, int out_size)
{
    const float* hV   = (const float*)d_in[0];
    const float* hE   = (const float*)d_in[1];
    const int*   mask = (const int*)  d_in[2];
    const float* WQ   = (const float*)d_in[3];
    const float* WK   = (const float*)d_in[4];
    const float* WV   = (const float*)d_in[5];
    const float* WO   = (const float*)d_in[6];
    float*       out  = (float*)d_out;

    const int N = in_sizes[0] / HDIM;
    if (N <= 0) return;

    float *Q, *Qt, *Ctx, *Vout;
    cudaGetSymbolAddress((void**)&Q,    g_Q);
    cudaGetSymbolAddress((void**)&Qt,   g_Qt);
    cudaGetSymbolAddress((void**)&Ctx,  g_ctx);
    cudaGetSymbolAddress((void**)&Vout, g_vout);

    const int MB64  = (N + 63) / 64;
    const int MB128 = (N + 127) / 128;
    const float inv_sqrt_d = 0.17677669529663687f;  // 1/sqrt(32)

    // 1) Q = h_V @ W_Q^T
    sgemm_kernel<64, 128, 16, 8, 8, true><<<dim3(1, MB64, 1), 128>>>(
        hV, WQ, Q, N, 128, 128, 128, 128, 128, 0, 0, 0, 1.f);

    // 2) Qt[n, h*128+b] = (1/sqrt(d)) * Q[n,32h:32h+32] @ W_K[32h:32h+32,:]
    sgemm_kernel<64, 128, 16, 8, 8, false><<<dim3(1, MB64, 4), 128>>>(
        Q, WK, Qt, N, 128, 32, 128, 128, 512,
        /*aB=*/32, /*bB=*/32 * 128, /*cB=*/128, inv_sqrt_d);

    // 3) persistent fused attention -> ctx[N,512]  (6 CTAs/SM)
    int attn_grid = 888;
    if (attn_grid > N) attn_grid = N;
    attn_kernel<<<attn_grid, 128>>>(hE, mask, Qt, Ctx, N);

    // 4) vout[n, 32h+j] = ctx[n, 128h:] @ W_V[32h+j,:]
    sgemm_kernel<128, 32, 16, 8, 4, true><<<dim3(1, MB128, 4), 128>>>(
        Ctx, WV, Vout, N, 32, 128, 512, 128, 128,
        /*aB=*/128, /*bB=*/32 * 128, /*cB=*/32, 1.f);

    // 5) out = vout @ W_O^T
    sgemm_kernel<64, 128, 16, 8, 8, true><<<dim3(1, MB64, 1), 128>>>(
        Vout, WO, out, N, 128, 128, 128, 128, 128, 0, 0, 0, 1.f);
}

// round 15
// speedup vs baseline: 1.0827x; 1.0827x over previous
#include <cuda_runtime.h>

// ----------------------------------------------------------------------------
// NeighborAttention (63 GFLOP -> 3.9 GFLOP), 5 launches:
//   1) Q   = hV @ WQ^T
//   2) Qt  = (1/sqrt(32)) * Q_h @ WK_h
//   3) attn: persistent, pipelined (R10-proven form, untouched)
//   4) vout = ctx_h @ WV_h^T
//   5) out  = vout @ WO^T
// This round: register double-buffering in sgemm_kernel (prefetch next tile's
// global loads during compute) — the GEMMs' exposed-LDG latency was the
// binding stall (fma 36%, L1 59%, occ 35%).
// ----------------------------------------------------------------------------

#define MAXN 30720
#define HDIM 128
#define KNB 32

__device__ float g_Q[MAXN * 128];
__device__ float g_Qt[MAXN * 512];
__device__ float g_ctx[MAXN * 512];
__device__ float g_vout[MAXN * 128];

// ----------------------------------------------------------------------------
// Tiled SGEMM, 8x8 / 8x4 register microtiles, register double-buffered.
// ----------------------------------------------------------------------------
template <int BM, int BN, int BK, int TM, int TN, bool TRANSB>
__global__ void __launch_bounds__((BM / TM) * (BN / TN)) sgemm_kernel(
    const float* __restrict__ A, const float* __restrict__ B, float* __restrict__ C,
    int M, int Nc, int K, int lda, int ldb, int ldc,
    long long aB, long long bB, long long cB, float alpha)
{
    constexpr int NT = (BM / TM) * (BN / TN);
    constexpr int A4 = (BM * BK) / (4 * NT);
    constexpr int B4 = TRANSB ? (BN * BK) / (4 * NT) : (BK * BN) / (4 * NT);

    __shared__ float As[BK][BM + 4];
    __shared__ float Bs[BK][BN + 4];

    const long long bz = blockIdx.z;
    A += bz * aB; B += bz * bB; C += bz * cB;

    const int m0 = blockIdx.y * BM;
    const int n0 = blockIdx.x * BN;
    const int t  = threadIdx.x;
    const int tm = t / (BN / TN);
    const int tn = t % (BN / TN);

    float acc[TM][TN] = {};
    float4 areg[A4];
    float4 breg[B4];

    // ---- prologue: load tile k0=0 into registers ----
    #pragma unroll
    for (int i = 0; i < A4; i++) {
        int idx4 = t + NT * i;
        int r  = idx4 / (BK / 4);
        int kc = (idx4 % (BK / 4)) * 4;
        areg[i] = make_float4(0.f, 0.f, 0.f, 0.f);
        if (m0 + r < M) areg[i] = *(const float4*)&A[(long long)(m0 + r) * lda + kc];
    }
    #pragma unroll
    for (int i = 0; i < B4; i++) {
        int idx4 = t + NT * i;
        breg[i] = make_float4(0.f, 0.f, 0.f, 0.f);
        if (!TRANSB) {
            int kr = idx4 / (BN / 4);
            int nc = (idx4 % (BN / 4)) * 4;
            if (n0 + nc < Nc) breg[i] = *(const float4*)&B[(long long)kr * ldb + n0 + nc];
        } else {
            int n  = idx4 / (BK / 4);
            int kc = (idx4 % (BK / 4)) * 4;
            if (n0 + n < Nc) breg[i] = *(const float4*)&B[(long long)(n0 + n) * ldb + kc];
        }
    }

    for (int k0 = 0; k0 < K; k0 += BK) {
        // ---- commit current tile registers to smem ----
        #pragma unroll
        for (int i = 0; i < A4; i++) {
            int idx4 = t + NT * i;
            int r  = idx4 / (BK / 4);
            int kc = (idx4 % (BK / 4)) * 4;
            As[kc + 0][r] = areg[i].x;
            As[kc + 1][r] = areg[i].y;
            As[kc + 2][r] = areg[i].z;
            As[kc + 3][r] = areg[i].w;
        }
        #pragma unroll
        for (int i = 0; i < B4; i++) {
            int idx4 = t + NT * i;
            if (!TRANSB) {
                int kr = idx4 / (BN / 4);
                int nc = (idx4 % (BN / 4)) * 4;
                *(float4*)&Bs[kr][nc] = breg[i];
            } else {
                int n  = idx4 / (BK / 4);
                int kc = (idx4 % (BK / 4)) * 4;
                Bs[kc + 0][n] = breg[i].x;
                Bs[kc + 1][n] = breg[i].y;
                Bs[kc + 2][n] = breg[i].z;
                Bs[kc + 3][n] = breg[i].w;
            }
        }
        __syncthreads();

        // ---- issue next tile's global loads (retire during compute) ----
        const int kn = k0 + BK;
        if (kn < K) {
            #pragma unroll
            for (int i = 0; i < A4; i++) {
                int idx4 = t + NT * i;
                int r  = idx4 / (BK / 4);
                int kc = (idx4 % (BK / 4)) * 4;
                areg[i] = make_float4(0.f, 0.f, 0.f, 0.f);
                if (m0 + r < M) areg[i] = *(const float4*)&A[(long long)(m0 + r) * lda + kn + kc];
            }
            #pragma unroll
            for (int i = 0; i < B4; i++) {
                int idx4 = t + NT * i;
                breg[i] = make_float4(0.f, 0.f, 0.f, 0.f);
                if (!TRANSB) {
                    int kr = idx4 / (BN / 4);
                    int nc = (idx4 % (BN / 4)) * 4;
                    if (n0 + nc < Nc) breg[i] = *(const float4*)&B[(long long)(kn + kr) * ldb + n0 + nc];
                } else {
                    int n  = idx4 / (BK / 4);
                    int kc = (idx4 % (BK / 4)) * 4;
                    if (n0 + n < Nc) breg[i] = *(const float4*)&B[(long long)(n0 + n) * ldb + kn + kc];
                }
            }
        }

        // ---- compute from smem ----
        #pragma unroll
        for (int kk = 0; kk < BK; kk++) {
            float a[TM], b[TN];
            #pragma unroll
            for (int h = 0; h < TM / 4; h++) {
                float4 v = *(const float4*)&As[kk][tm * 4 + h * (BM / 2)];
                a[h * 4 + 0] = v.x; a[h * 4 + 1] = v.y;
                a[h * 4 + 2] = v.z; a[h * 4 + 3] = v.w;
            }
            #pragma unroll
            for (int h = 0; h < TN / 4; h++) {
                float4 v = *(const float4*)&Bs[kk][tn * 4 + h * (BN / 2)];
                b[h * 4 + 0] = v.x; b[h * 4 + 1] = v.y;
                b[h * 4 + 2] = v.z; b[h * 4 + 3] = v.w;
            }
            #pragma unroll
            for (int i = 0; i < TM; i++)
                #pragma unroll
                for (int j = 0; j < TN; j++)
                    acc[i][j] += a[i] * b[j];
        }
        __syncthreads();
    }

    #pragma unroll
    for (int i = 0; i < TM; i++) {
        int r = m0 + tm * 4 + (i / 4) * (BM / 2) + (i % 4);
        if (r >= M) continue;
        #pragma unroll
        for (int jh = 0; jh < TN / 4; jh++) {
            int c = n0 + tn * 4 + jh * (BN / 2);
            if (c < Nc) {
                float4 v = make_float4(acc[i][jh * 4 + 0] * alpha, acc[i][jh * 4 + 1] * alpha,
                                       acc[i][jh * 4 + 2] * alpha, acc[i][jh * 4 + 3] * alpha);
                *(float4*)&C[(long long)r * ldc + c] = v;
            }
        }
    }
}

// ----------------------------------------------------------------------------
// Persistent fused neighbor attention — exact R10 form (measured 141.7us;
// R12 predication and R13 shuffles both regressed it).
// ----------------------------------------------------------------------------
__global__ void __launch_bounds__(128) attn_kernel(
    const float* __restrict__ hE, const int* __restrict__ mask,
    const float* __restrict__ Qt, float* __restrict__ ctx, int N)
{
    __shared__ float Es[32 * 132];
    __shared__ float Qts[4 * 132];
    __shared__ float Lp[512];
    __shared__ float Asm[128];
    __shared__ int   msk[3][32];

    const int t  = threadIdx.x;
    const int G  = gridDim.x;
    const int n0 = blockIdx.x;
    if (n0 >= N) return;

    if (t < 32) {
        msk[0][t] = mask[(long long)n0 * KNB + t];
        long long n1 = n0 + (long long)G;
        msk[1][t] = (n1 < N) ? mask[n1 * KNB + t] : 0;
    }
    __syncthreads();

    float4 ereg[8];
    float4 qreg;

    {
        const float* e = hE + (long long)n0 * (KNB * HDIM);
        #pragma unroll
        for (int ii = 0; ii < 8; ii++) {
            int idx4 = t + 128 * ii;
            int k = idx4 >> 5;
            ereg[ii] = make_float4(0.f, 0.f, 0.f, 0.f);
            if (msk[0][k]) ereg[ii] = *(const float4*)&e[idx4 << 2];
        }
        qreg = *(const float4*)&Qt[(long long)n0 * 512 + t * 4];
        #pragma unroll
        for (int ii = 0; ii < 8; ii++) {
            int idx4 = t + 128 * ii;
            int k = idx4 >> 5, a4 = idx4 & 31;
            *(float4*)&Es[k * 132 + (a4 << 2)] = ereg[ii];
        }
        int h = t >> 5, a4 = t & 31;
        *(float4*)&Qts[h * 132 + (a4 << 2)] = qreg;
    }
    __syncthreads();

    for (int i = 0; ; i++) {
        const long long n  = n0 + (long long)i * G;
        const long long nn = n + G;
        const bool has_next = (nn < N);
        int mreg = 0;

        if (has_next) {
            const int s1 = (i + 1) % 3;
            const float* e = hE + nn * (KNB * HDIM);
            #pragma unroll
            for (int ii = 0; ii < 8; ii++) {
                int idx4 = t + 128 * ii;
                int k = idx4 >> 5;
                ereg[ii] = make_float4(0.f, 0.f, 0.f, 0.f);
                if (msk[s1][k]) ereg[ii] = *(const float4*)&e[idx4 << 2];
            }
            qreg = *(const float4*)&Qt[nn * 512 + t * 4];
            if (t < 32) {
                long long n2 = n + 2LL * G;
                mreg = (n2 < N) ? mask[n2 * KNB + t] : 0;
            }
        }

        const int* mc = msk[i % 3];

        {
            const int ac = t >> 5;
            const int k  = t & 31;
            const float* ep = &Es[k * 132 + (ac << 5)];
            float p0 = 0.f, p1 = 0.f, p2 = 0.f, p3 = 0.f;
            #pragma unroll
            for (int s = 0; s < 8; s++) {
                float4 e4 = *(const float4*)&ep[s << 2];
                int ao = (ac << 5) + (s << 2);
                float4 q0 = *(const float4*)&Qts[0 * 132 + ao];
                float4 q1 = *(const float4*)&Qts[1 * 132 + ao];
                float4 q2 = *(const float4*)&Qts[2 * 132 + ao];
                float4 q3 = *(const float4*)&Qts[3 * 132 + ao];
                p0 += q0.x * e4.x + q0.y * e4.y + q0.z * e4.z + q0.w * e4.w;
                p1 += q1.x * e4.x + q1.y * e4.y + q1.z * e4.z + q1.w * e4.w;
                p2 += q2.x * e4.x + q2.y * e4.y + q2.z * e4.z + q2.w * e4.w;
                p3 += q3.x * e4.x + q3.y * e4.y + q3.z * e4.z + q3.w * e4.w;
            }
            Lp[(ac << 7) + 0 * 32 + k] = p0;
            Lp[(ac << 7) + 1 * 32 + k] = p1;
            Lp[(ac << 7) + 2 * 32 + k] = p2;
            Lp[(ac << 7) + 3 * 32 + k] = p3;
        }
        __syncthreads();

        {
            const int h = t >> 5, k = t & 31;
            float x = Lp[0 * 128 + h * 32 + k] + Lp[1 * 128 + h * 32 + k]
                    + Lp[2 * 128 + h * 32 + k] + Lp[3 * 128 + h * 32 + k];
            bool mv  = (mc[k] != 0);
            float xm = mv ? x : -3.402823466e+38f;
            float mx = xm;
            #pragma unroll
            for (int o = 16; o > 0; o >>= 1) mx = fmaxf(mx, __shfl_xor_sync(0xffffffffu, mx, o));
            float p = mv ? __expf(xm - mx) : 0.f;
            float sm = p;
            #pragma unroll
            for (int o = 16; o > 0; o >>= 1) sm += __shfl_xor_sync(0xffffffffu, sm, o);
            float inv = (sm > 0.f) ? (1.f / sm) : 0.f;
            Asm[h * 32 + k] = p * inv;
        }
        __syncthreads();

        {
            float c0 = 0.f, c1 = 0.f, c2 = 0.f, c3 = 0.f;
            #pragma unroll
            for (int k4 = 0; k4 < 8; k4++) {
                float4 a0 = *(const float4*)&Asm[0 * 32 + (k4 << 2)];
                float4 a1 = *(const float4*)&Asm[1 * 32 + (k4 << 2)];
                float4 a2 = *(const float4*)&Asm[2 * 32 + (k4 << 2)];
                float4 a3 = *(const float4*)&Asm[3 * 32 + (k4 << 2)];
                float w0[4] = {a0.x, a0.y, a0.z, a0.w};
                float w1[4] = {a1.x, a1.y, a1.z, a1.w};
                float w2[4] = {a2.x, a2.y, a2.z, a2.w};
                float w3[4] = {a3.x, a3.y, a3.z, a3.w};
                #pragma unroll
                for (int ii = 0; ii < 4; ii++) {
                    float ev = Es[((k4 << 2) + ii) * 132 + t];
                    c0 += w0[ii] * ev;
                    c1 += w1[ii] * ev;
                    c2 += w2[ii] * ev;
                    c3 += w3[ii] * ev;
                }
            }
            float* cp = ctx + n * 512 + t;
            cp[0]   = c0;
            cp[128] = c1;
            cp[256] = c2;
            cp[384] = c3;
        }

        if (!has_next) break;

        __syncthreads();
        #pragma unroll
        for (int ii = 0; ii < 8; ii++) {
            int idx4 = t + 128 * ii;
            int k = idx4 >> 5, a4 = idx4 & 31;
            *(float4*)&Es[k * 132 + (a4 << 2)] = ereg[ii];
        }
        {
            int h = t >> 5, a4 = t & 31;
            *(float4*)&Qts[h * 132 + (a4 << 2)] = qreg;
        }
        if (t < 32) msk[(i + 2) % 3][t] = mreg;
        __syncthreads();
    }
}

// ----------------------------------------------------------------------------
extern "C" void kernel_launch(void* const* d_in, const int* in_sizes, int n_in,
                              void* d_out, int out_size)
{
    const float* hV   = (const float*)d_in[0];
    const float* hE   = (const float*)d_in[1];
    const int*   mask = (const int*)  d_in[2];
    const float* WQ   = (const float*)d_in[3];
    const float* WK   = (const float*)d_in[4];
    const float* WV   = (const float*)d_in[5];
    const float* WO   = (const float*)d_in[6];
    float*       out  = (float*)d_out;

    const int N = in_sizes[0] / HDIM;
    if (N <= 0) return;

    float *Q, *Qt, *Ctx, *Vout;
    cudaGetSymbolAddress((void**)&Q,    g_Q);
    cudaGetSymbolAddress((void**)&Qt,   g_Qt);
    cudaGetSymbolAddress((void**)&Ctx,  g_ctx);
    cudaGetSymbolAddress((void**)&Vout, g_vout);

    const int MB64  = (N + 63) / 64;
    const int MB128 = (N + 127) / 128;
    const float inv_sqrt_d = 0.17677669529663687f;  // 1/sqrt(32)

    // 1) Q = h_V @ W_Q^T
    sgemm_kernel<64, 128, 16, 8, 8, true><<<dim3(1, MB64, 1), 128>>>(
        hV, WQ, Q, N, 128, 128, 128, 128, 128, 0, 0, 0, 1.f);

    // 2) Qt[n, h*128+b] = (1/sqrt(d)) * Q[n,32h:32h+32] @ W_K[32h:32h+32,:]
    sgemm_kernel<64, 128, 16, 8, 8, false><<<dim3(1, MB64, 4), 128>>>(
        Q, WK, Qt, N, 128, 32, 128, 128, 512,
        /*aB=*/32, /*bB=*/32 * 128, /*cB=*/128, inv_sqrt_d);

    // 3) persistent fused attention -> ctx[N,512]
    int attn_grid = 888;
    if (attn_grid > N) attn_grid = N;
    attn_kernel<<<attn_grid, 128>>>(hE, mask, Qt, Ctx, N);

    // 4) vout[n, 32h+j] = ctx[n, 128h:] @ W_V[32h+j,:]
    sgemm_kernel<128, 32, 16, 8, 4, true><<<dim3(1, MB128, 4), 128>>>(
        Ctx, WV, Vout, N, 32, 128, 512, 128, 128,
        /*aB=*/128, /*bB=*/32 * 128, /*cB=*/32, 1.f);

    // 5) out = vout @ W_O^T
    sgemm_kernel<64, 128, 16, 8, 8, true><<<dim3(1, MB64, 1), 128>>>(
        Vout, WO, out, N, 128, 128, 128, 128, 128, 0, 0, 0, 1.f);
}